// round 1
// baseline (speedup 1.0000x reference)
#include <cuda_runtime.h>
#include <math.h>

// ---------------------------------------------------------------------------
// Problem constants (fixed shapes for this problem instance)
// ---------------------------------------------------------------------------
#define BATCH 4
#define SEQ   2048
#define DIN   256
#define HID   512
#define DOUT  256
#define NHEAD 8
#define DH    64
#define CAP   128          // adjacency bucket capacity (max degree ~60 for E/N=32)
#define TOK   (BATCH*SEQ)  // 8192 tokens

// ---------------------------------------------------------------------------
// Scratch (static device globals; no runtime allocation allowed)
// ---------------------------------------------------------------------------
__device__ float g_xl  [TOK*HID];     // x @ W_gcn
__device__ float g_h   [TOK*HID];     // GCN output
__device__ float g_qkv [TOK*3*HID];   // fused QKV
__device__ float g_ao  [TOK*HID];     // attention output
__device__ float g_proj[TOK*HID];     // out_proj + relu
__device__ float g_dinv[SEQ];
__device__ int   g_cnt [SEQ];
__device__ int   g_cur [SEQ];
__device__ int   g_slot[SEQ*CAP];

// ---------------------------------------------------------------------------
// Graph bookkeeping kernels
// ---------------------------------------------------------------------------
__global__ void k_zero() {
    int i = blockIdx.x * blockDim.x + threadIdx.x;
    if (i < SEQ) { g_cnt[i] = 0; g_cur[i] = 0; }
}

__global__ void k_count(const int* __restrict__ dst, int E) {
    int i = blockIdx.x * blockDim.x + threadIdx.x;
    if (i < E) atomicAdd(&g_cnt[dst[i]], 1);
}

__global__ void k_dinv() {
    int i = blockIdx.x * blockDim.x + threadIdx.x;
    if (i < SEQ) g_dinv[i] = rsqrtf((float)(g_cnt[i] + 1));  // +1 = self loop
}

__global__ void k_fill(const int* __restrict__ src, const int* __restrict__ dst, int E) {
    int i = blockIdx.x * blockDim.x + threadIdx.x;
    if (i < E) {
        int d = dst[i];
        int p = atomicAdd(&g_cur[d], 1);
        if (p < CAP) g_slot[d * CAP + p] = src[i];
    }
}

// ---------------------------------------------------------------------------
// GCN aggregation: h[b,n,:] = dinv[n]*sum_e dinv[src]*xl[b,src,:]
//                           + dinv[n]^2 * xl[b,n,:] + bias
// One block per (n, b); 128 threads, each handling 4 contiguous floats.
// ---------------------------------------------------------------------------
__global__ void k_agg(const float* __restrict__ bias) {
    int n = blockIdx.x, b = blockIdx.y, t = threadIdx.x;
    const float4* x4 = (const float4*)g_xl;
    size_t base = (size_t)b * SEQ * (HID/4);
    int cnt = g_cnt[n]; if (cnt > CAP) cnt = CAP;
    float4 acc = make_float4(0.f, 0.f, 0.f, 0.f);
    const int* slot = &g_slot[n * CAP];
    for (int e = 0; e < cnt; e++) {
        int s = slot[e];
        float w = g_dinv[s];
        float4 v = x4[base + (size_t)s * (HID/4) + t];
        acc.x += w * v.x; acc.y += w * v.y; acc.z += w * v.z; acc.w += w * v.w;
    }
    float dv = g_dinv[n], dv2 = dv * dv;
    float4 self = x4[base + (size_t)n * (HID/4) + t];
    float4 bs = ((const float4*)bias)[t];
    float4 r;
    r.x = dv * acc.x + dv2 * self.x + bs.x;
    r.y = dv * acc.y + dv2 * self.y + bs.y;
    r.z = dv * acc.z + dv2 * self.z + bs.z;
    r.w = dv * acc.w + dv2 * self.w + bs.w;
    ((float4*)g_h)[base + (size_t)n * (HID/4) + t] = r;
}

// ---------------------------------------------------------------------------
// Tiled fp32 GEMM: C[M,Nn] = A[M,K] * op(B) (+bias) (+relu)
//   BT=true : B stored [Nn,K] (use B^T, i.e. C = A*B^T)  — torch Linear weights
//   BT=false: B stored [K,Nn]
// 64x64 tile, BK=32, 256 threads, 4x4 microtile, float4 smem reads.
// Requires M%64==0, Nn%64==0, K%32==0 (true for all calls here).
// ---------------------------------------------------------------------------
template<bool BT, bool BIAS, bool RELU>
__global__ void gemm64(const float* __restrict__ A, const float* __restrict__ B,
                       const float* __restrict__ bias, float* __restrict__ C,
                       int M, int Nn, int K) {
    __shared__ __align__(16) float As[32][68];
    __shared__ __align__(16) float Bs[32][68];
    int tid = threadIdx.x;
    int ty = tid >> 4, tx = tid & 15;
    int mBase = blockIdx.y * 64, nBase = blockIdx.x * 64;
    float acc[4][4] = {};

    for (int k0 = 0; k0 < K; k0 += 32) {
        // A tile: 64 rows x 32 k, transposed into As[k][m]
        #pragma unroll
        for (int i = 0; i < 2; i++) {
            int id = tid * 2 + i;          // 0..511 float4s
            int m = id >> 3, k4 = id & 7;
            float4 v = *(const float4*)&A[(size_t)(mBase + m) * K + k0 + k4 * 4];
            As[k4*4+0][m] = v.x; As[k4*4+1][m] = v.y;
            As[k4*4+2][m] = v.z; As[k4*4+3][m] = v.w;
        }
        if (BT) {
            #pragma unroll
            for (int i = 0; i < 2; i++) {
                int id = tid * 2 + i;
                int c = id >> 3, k4 = id & 7;
                float4 v = *(const float4*)&B[(size_t)(nBase + c) * K + k0 + k4 * 4];
                Bs[k4*4+0][c] = v.x; Bs[k4*4+1][c] = v.y;
                Bs[k4*4+2][c] = v.z; Bs[k4*4+3][c] = v.w;
            }
        } else {
            #pragma unroll
            for (int i = 0; i < 2; i++) {
                int id = tid * 2 + i;      // 32 k x 16 c4
                int k = id >> 4, c4 = id & 15;
                float4 v = *(const float4*)&B[(size_t)(k0 + k) * Nn + nBase + c4 * 4];
                *(float4*)&Bs[k][c4 * 4] = v;
            }
        }
        __syncthreads();
        #pragma unroll
        for (int k = 0; k < 32; k++) {
            float4 av = *(const float4*)&As[k][ty * 4];
            float4 bv = *(const float4*)&Bs[k][tx * 4];
            float ar[4] = {av.x, av.y, av.z, av.w};
            float br[4] = {bv.x, bv.y, bv.z, bv.w};
            #pragma unroll
            for (int i = 0; i < 4; i++)
                #pragma unroll
                for (int j = 0; j < 4; j++)
                    acc[i][j] += ar[i] * br[j];
        }
        __syncthreads();
    }

    float4 bb = make_float4(0.f, 0.f, 0.f, 0.f);
    if (BIAS) bb = *(const float4*)&bias[nBase + tx * 4];
    #pragma unroll
    for (int i = 0; i < 4; i++) {
        float4 o;
        o.x = acc[i][0] + bb.x; o.y = acc[i][1] + bb.y;
        o.z = acc[i][2] + bb.z; o.w = acc[i][3] + bb.w;
        if (RELU) {
            o.x = fmaxf(o.x, 0.f); o.y = fmaxf(o.y, 0.f);
            o.z = fmaxf(o.z, 0.f); o.w = fmaxf(o.w, 0.f);
        }
        *(float4*)&C[(size_t)(mBase + ty * 4 + i) * Nn + nBase + tx * 4] = o;
    }
}

// ---------------------------------------------------------------------------
// Flash attention, fp32, 64-query x 64-key tiles, dh=64.
// qkv layout: [B, N, 3*HID] with q|k|v each [NHEAD, DH] per token.
// grid = (SEQ/64, NHEAD, BATCH), 256 threads, 4x4 microtile per thread.
// Dynamic smem: Qt[64][68] + Kt[64][68] + Vs[64][68] + Ss[64][68] = 69632 B.
// ---------------------------------------------------------------------------
#define FA_SMEM (4 * 64 * 68 * 4)

__global__ void flash_attn(const float* __restrict__ qkv, float* __restrict__ out) {
    extern __shared__ __align__(16) float sm[];
    float* Qt = sm;                // [d][r] (scaled by 1/8)
    float* Kt = sm + 64 * 68;      // [d][c]
    float* Vs = sm + 2 * 64 * 68;  // [c][d]
    float* Ss = sm + 3 * 64 * 68;  // [r][c] (exp'd probs)

    int tid = threadIdx.x;
    int ty = tid >> 4, tx = tid & 15;
    int n0 = blockIdx.x * 64;
    int hh = blockIdx.y;
    int b  = blockIdx.z;

    const float* qbase = qkv + (size_t)b * SEQ * (3 * HID) + hh * DH;
    const float* kbase = qbase + HID;
    const float* vbase = qbase + 2 * HID;

    // Load Q tile (scaled), transposed to [d][r]
    #pragma unroll
    for (int i = 0; i < 4; i++) {
        int id = tid + i * 256;           // 0..1023
        int r = id >> 4, d4 = id & 15;
        float4 v = *(const float4*)&qbase[(size_t)(n0 + r) * (3 * HID) + d4 * 4];
        Qt[(d4*4+0)*68 + r] = v.x * 0.125f;
        Qt[(d4*4+1)*68 + r] = v.y * 0.125f;
        Qt[(d4*4+2)*68 + r] = v.z * 0.125f;
        Qt[(d4*4+3)*68 + r] = v.w * 0.125f;
    }

    float m[4], l[4], o[4][4];
    #pragma unroll
    for (int i = 0; i < 4; i++) {
        m[i] = -3.0e38f; l[i] = 0.f;
        #pragma unroll
        for (int j = 0; j < 4; j++) o[i][j] = 0.f;
    }

    for (int t0 = 0; t0 < SEQ; t0 += 64) {
        // Load K (transposed) and V (direct)
        #pragma unroll
        for (int i = 0; i < 4; i++) {
            int id = tid + i * 256;
            int c = id >> 4, d4 = id & 15;
            float4 v = *(const float4*)&kbase[(size_t)(t0 + c) * (3 * HID) + d4 * 4];
            Kt[(d4*4+0)*68 + c] = v.x;
            Kt[(d4*4+1)*68 + c] = v.y;
            Kt[(d4*4+2)*68 + c] = v.z;
            Kt[(d4*4+3)*68 + c] = v.w;
            float4 w = *(const float4*)&vbase[(size_t)(t0 + c) * (3 * HID) + d4 * 4];
            *(float4*)&Vs[c * 68 + d4 * 4] = w;
        }
        __syncthreads();

        // S = Q K^T (scale already in Q)
        float s[4][4] = {};
        #pragma unroll
        for (int d = 0; d < 64; d++) {
            float4 av = *(const float4*)&Qt[d * 68 + ty * 4];
            float4 bv = *(const float4*)&Kt[d * 68 + tx * 4];
            float ar[4] = {av.x, av.y, av.z, av.w};
            float br[4] = {bv.x, bv.y, bv.z, bv.w};
            #pragma unroll
            for (int i = 0; i < 4; i++)
                #pragma unroll
                for (int j = 0; j < 4; j++)
                    s[i][j] += ar[i] * br[j];
        }

        // Online softmax per row (row shared across 16-lane tx group)
        #pragma unroll
        for (int i = 0; i < 4; i++) {
            float tmax = fmaxf(fmaxf(s[i][0], s[i][1]), fmaxf(s[i][2], s[i][3]));
            #pragma unroll
            for (int off = 8; off >= 1; off >>= 1)
                tmax = fmaxf(tmax, __shfl_xor_sync(0xffffffffu, tmax, off, 16));
            float mn = fmaxf(m[i], tmax);
            float corr = __expf(m[i] - mn);
            float p0 = __expf(s[i][0] - mn);
            float p1 = __expf(s[i][1] - mn);
            float p2 = __expf(s[i][2] - mn);
            float p3 = __expf(s[i][3] - mn);
            float rs = p0 + p1 + p2 + p3;
            #pragma unroll
            for (int off = 8; off >= 1; off >>= 1)
                rs += __shfl_xor_sync(0xffffffffu, rs, off, 16);
            l[i] = l[i] * corr + rs;
            m[i] = mn;
            o[i][0] *= corr; o[i][1] *= corr; o[i][2] *= corr; o[i][3] *= corr;
            float4 pv = make_float4(p0, p1, p2, p3);
            *(float4*)&Ss[(ty * 4 + i) * 68 + tx * 4] = pv;
        }
        __syncthreads();

        // O += P V
        #pragma unroll
        for (int c = 0; c < 64; c++) {
            float4 v = *(const float4*)&Vs[c * 68 + tx * 4];
            #pragma unroll
            for (int i = 0; i < 4; i++) {
                float p = Ss[(ty * 4 + i) * 68 + c];
                o[i][0] += p * v.x; o[i][1] += p * v.y;
                o[i][2] += p * v.z; o[i][3] += p * v.w;
            }
        }
        __syncthreads();
    }

    #pragma unroll
    for (int i = 0; i < 4; i++) {
        float inv = 1.0f / l[i];
        float4 r = make_float4(o[i][0]*inv, o[i][1]*inv, o[i][2]*inv, o[i][3]*inv);
        *(float4*)&out[(size_t)(b * SEQ + n0 + ty * 4 + i) * HID + hh * DH + tx * 4] = r;
    }
}

// ---------------------------------------------------------------------------
// Host launch
// ---------------------------------------------------------------------------
extern "C" void kernel_launch(void* const* d_in, const int* in_sizes, int n_in,
                              void* d_out, int out_size) {
    const float* x  = (const float*)d_in[0];
    const int*   ei = (const int*)  d_in[1];
    const float* Wg = (const float*)d_in[2];
    const float* bg = (const float*)d_in[3];
    const float* wi = (const float*)d_in[4];
    const float* bi = (const float*)d_in[5];
    const float* wo = (const float*)d_in[6];
    const float* bo = (const float*)d_in[7];
    const float* fw = (const float*)d_in[8];
    const float* fb = (const float*)d_in[9];
    float* out = (float*)d_out;
    int E = in_sizes[1] / 2;

    void *p_xl, *p_h, *p_qkv, *p_ao, *p_proj;
    cudaGetSymbolAddress(&p_xl,   g_xl);
    cudaGetSymbolAddress(&p_h,    g_h);
    cudaGetSymbolAddress(&p_qkv,  g_qkv);
    cudaGetSymbolAddress(&p_ao,   g_ao);
    cudaGetSymbolAddress(&p_proj, g_proj);

    cudaFuncSetAttribute(flash_attn, cudaFuncAttributeMaxDynamicSharedMemorySize, FA_SMEM);

    // 1) Graph structure
    k_zero <<<(SEQ + 255) / 256, 256>>>();
    k_count<<<(E   + 255) / 256, 256>>>(ei + E, E);
    k_dinv <<<(SEQ + 255) / 256, 256>>>();
    k_fill <<<(E   + 255) / 256, 256>>>(ei, ei + E, E);

    // 2) GCN linear: xl = x @ W_gcn   (NN, no bias)
    gemm64<false, false, false><<<dim3(HID / 64, TOK / 64), 256>>>(
        x, Wg, nullptr, (float*)p_xl, TOK, HID, DIN);

    // 3) GCN aggregation (+bias)
    k_agg<<<dim3(SEQ, BATCH), 128>>>(bg);

    // 4) QKV: qkv = h @ wi^T + bi   (NT, bias)
    gemm64<true, true, false><<<dim3(3 * HID / 64, TOK / 64), 256>>>(
        (const float*)p_h, wi, bi, (float*)p_qkv, TOK, 3 * HID, HID);

    // 5) Flash attention
    flash_attn<<<dim3(SEQ / 64, NHEAD, BATCH), 256, FA_SMEM>>>(
        (const float*)p_qkv, (float*)p_ao);

    // 6) out_proj + relu: proj = relu(ao @ wo^T + bo)  (NT, bias, relu)
    gemm64<true, true, true><<<dim3(HID / 64, TOK / 64), 256>>>(
        (const float*)p_ao, wo, bo, (float*)p_proj, TOK, HID, HID);

    // 7) fc: out = proj @ fw + fb    (NN, bias)
    gemm64<false, true, false><<<dim3(DOUT / 64, TOK / 64), 256>>>(
        (const float*)p_proj, fw, fb, out, TOK, DOUT, HID);
}

// round 3
// speedup vs baseline: 2.4923x; 2.4923x over previous
#include <cuda_runtime.h>
#include <math.h>
#include <stdint.h>

// ---------------------------------------------------------------------------
// Problem constants
// ---------------------------------------------------------------------------
#define BATCH 4
#define SEQ   2048
#define DIN   256
#define HID   512
#define DOUT  256
#define NHEAD 8
#define DH    64
#define CAP   128
#define TOK   (BATCH*SEQ)

// ---------------------------------------------------------------------------
// Scratch
// ---------------------------------------------------------------------------
__device__ float g_xl  [TOK*HID];
__device__ float g_h   [TOK*HID];
__device__ float g_qkv [TOK*3*HID];
__device__ float g_ao  [TOK*HID];
__device__ float g_proj[TOK*HID];
__device__ float g_dinv[SEQ];
__device__ int   g_cnt [SEQ];
__device__ int   g_cur [SEQ];
__device__ int   g_slot[SEQ*CAP];

// ---------------------------------------------------------------------------
// Helpers: tf32 convert + m16n8k8 tf32 MMA
// ---------------------------------------------------------------------------
__device__ __forceinline__ uint32_t f2tf(float x) {
    uint32_t u;
    asm("cvt.rna.tf32.f32 %0, %1;" : "=r"(u) : "f"(x));
    return u;
}

__device__ __forceinline__ void mma8(float* c, const uint32_t* a,
                                     uint32_t b0, uint32_t b1) {
    asm volatile(
        "mma.sync.aligned.m16n8k8.row.col.f32.tf32.tf32.f32 "
        "{%0,%1,%2,%3}, {%4,%5,%6,%7}, {%8,%9}, {%0,%1,%2,%3};"
        : "+f"(c[0]), "+f"(c[1]), "+f"(c[2]), "+f"(c[3])
        : "r"(a[0]), "r"(a[1]), "r"(a[2]), "r"(a[3]), "r"(b0), "r"(b1));
}

// ---------------------------------------------------------------------------
// Graph bookkeeping
// ---------------------------------------------------------------------------
__global__ void k_zero() {
    int i = blockIdx.x * blockDim.x + threadIdx.x;
    if (i < SEQ) { g_cnt[i] = 0; g_cur[i] = 0; }
}
__global__ void k_count(const int* __restrict__ dst, int E) {
    int i = blockIdx.x * blockDim.x + threadIdx.x;
    if (i < E) atomicAdd(&g_cnt[dst[i]], 1);
}
__global__ void k_dinv() {
    int i = blockIdx.x * blockDim.x + threadIdx.x;
    if (i < SEQ) g_dinv[i] = rsqrtf((float)(g_cnt[i] + 1));
}
__global__ void k_fill(const int* __restrict__ src, const int* __restrict__ dst, int E) {
    int i = blockIdx.x * blockDim.x + threadIdx.x;
    if (i < E) {
        int d = dst[i];
        int p = atomicAdd(&g_cur[d], 1);
        if (p < CAP) g_slot[d * CAP + p] = src[i];
    }
}

// ---------------------------------------------------------------------------
// GCN aggregation (fp32, L2-resident gathers)
// ---------------------------------------------------------------------------
__global__ void k_agg(const float* __restrict__ bias) {
    int n = blockIdx.x, b = blockIdx.y, t = threadIdx.x;
    const float4* x4 = (const float4*)g_xl;
    size_t base = (size_t)b * SEQ * (HID/4);
    int cnt = g_cnt[n]; if (cnt > CAP) cnt = CAP;
    float4 acc = make_float4(0.f, 0.f, 0.f, 0.f);
    const int* slot = &g_slot[n * CAP];
    for (int e = 0; e < cnt; e++) {
        int s = slot[e];
        float w = g_dinv[s];
        float4 v = x4[base + (size_t)s * (HID/4) + t];
        acc.x += w * v.x; acc.y += w * v.y; acc.z += w * v.z; acc.w += w * v.w;
    }
    float dv = g_dinv[n], dv2 = dv * dv;
    float4 self = x4[base + (size_t)n * (HID/4) + t];
    float4 bs = ((const float4*)bias)[t];
    float4 r;
    r.x = dv * acc.x + dv2 * self.x + bs.x;
    r.y = dv * acc.y + dv2 * self.y + bs.y;
    r.z = dv * acc.z + dv2 * self.z + bs.z;
    r.w = dv * acc.w + dv2 * self.w + bs.w;
    ((float4*)g_h)[base + (size_t)n * (HID/4) + t] = r;
}

// ---------------------------------------------------------------------------
// tf32 tensor-core GEMM: C[M,Nn] = A[M,K] * op(B) (+bias) (+relu)
// BM=128 BN=64 BK=32, 256 threads = 8 warps (4M x 2N), warp tile 32x32.
// As row-major [m][40] (frag banks g*8+t, conflict-free).
// Bs k-major  [k][72] with col ^ ((k>>2)&7) swizzle (frag banks t*8+(g^s)+n0).
// ---------------------------------------------------------------------------
template<bool BT, bool BIAS, bool RELU>
__global__ __launch_bounds__(256)
void gemm_tf32(const float* __restrict__ A, const float* __restrict__ B,
               const float* __restrict__ bias, float* __restrict__ C,
               int M, int Nn, int K) {
    __shared__ uint32_t As[128][40];
    __shared__ uint32_t Bs[32][72];
    int tid = threadIdx.x, lane = tid & 31, wid = tid >> 5;
    int g = lane >> 2, t = lane & 3;
    int wm = wid >> 1, wn = wid & 1;
    int mBase = blockIdx.y * 128, nBase = blockIdx.x * 64;
    float acc[2][4][4] = {};

    for (int k0 = 0; k0 < K; k0 += 32) {
        // A tile: 128x32, row-major, vectorized uint4 store
        #pragma unroll
        for (int i = 0; i < 4; i++) {
            int idx = tid + i * 256;
            int m = idx >> 3, k4 = idx & 7;
            float4 v = *(const float4*)&A[(size_t)(mBase + m) * K + k0 + k4 * 4];
            uint4 u;
            u.x = f2tf(v.x); u.y = f2tf(v.y); u.z = f2tf(v.z); u.w = f2tf(v.w);
            *(uint4*)&As[m][k4 * 4] = u;
        }
        // B tile: k-major [k][n] with XOR swizzle
        if (BT) {   // B stored [Nn][K]
            #pragma unroll
            for (int i = 0; i < 2; i++) {
                int idx = tid + i * 256;
                int n = idx >> 3, k4 = idx & 7;
                float4 v = *(const float4*)&B[(size_t)(nBase + n) * K + k0 + k4 * 4];
                int cs = n ^ (k4 & 7);
                Bs[k4*4+0][cs] = f2tf(v.x);
                Bs[k4*4+1][cs] = f2tf(v.y);
                Bs[k4*4+2][cs] = f2tf(v.z);
                Bs[k4*4+3][cs] = f2tf(v.w);
            }
        } else {    // B stored [K][Nn]
            #pragma unroll
            for (int i = 0; i < 2; i++) {
                int idx = tid + i * 256;
                int k = idx >> 4, n4 = idx & 15;
                float4 v = *(const float4*)&B[(size_t)(k0 + k) * Nn + nBase + n4 * 4];
                int s = (k >> 2) & 7;
                Bs[k][(n4*4+0) ^ s] = f2tf(v.x);
                Bs[k][(n4*4+1) ^ s] = f2tf(v.y);
                Bs[k][(n4*4+2) ^ s] = f2tf(v.z);
                Bs[k][(n4*4+3) ^ s] = f2tf(v.w);
            }
        }
        __syncthreads();

        #pragma unroll
        for (int ks = 0; ks < 4; ks++) {
            int kb = ks * 8;
            uint32_t a[2][4];
            #pragma unroll
            for (int am = 0; am < 2; am++) {
                int m0 = wm * 32 + am * 16;
                a[am][0] = As[m0 + g    ][kb + t];
                a[am][1] = As[m0 + g + 8][kb + t];
                a[am][2] = As[m0 + g    ][kb + t + 4];
                a[am][3] = As[m0 + g + 8][kb + t + 4];
            }
            int s0 = (2 * ks) & 7, s1 = (2 * ks + 1) & 7;
            #pragma unroll
            for (int bn = 0; bn < 4; bn++) {
                int n0 = wn * 32 + bn * 8;
                uint32_t b0 = Bs[kb + t    ][(n0 + g) ^ s0];
                uint32_t b1 = Bs[kb + t + 4][(n0 + g) ^ s1];
                mma8(acc[0][bn], a[0], b0, b1);
                mma8(acc[1][bn], a[1], b0, b1);
            }
        }
        __syncthreads();
    }

    #pragma unroll
    for (int am = 0; am < 2; am++) {
        #pragma unroll
        for (int bn = 0; bn < 4; bn++) {
            int row = mBase + wm * 32 + am * 16 + g;
            int col = nBase + wn * 32 + bn * 8 + 2 * t;
            float b0v = 0.f, b1v = 0.f;
            if (BIAS) { b0v = bias[col]; b1v = bias[col + 1]; }
            float2 lo, hi;
            lo.x = acc[am][bn][0] + b0v; lo.y = acc[am][bn][1] + b1v;
            hi.x = acc[am][bn][2] + b0v; hi.y = acc[am][bn][3] + b1v;
            if (RELU) {
                lo.x = fmaxf(lo.x, 0.f); lo.y = fmaxf(lo.y, 0.f);
                hi.x = fmaxf(hi.x, 0.f); hi.y = fmaxf(hi.y, 0.f);
            }
            *(float2*)&C[(size_t)row * Nn + col]       = lo;
            *(float2*)&C[(size_t)(row + 8) * Nn + col] = hi;
        }
    }
}

// ---------------------------------------------------------------------------
// Flash attention, tf32 tensor cores.
// CTA = 128 threads (4 warps), Q tile 64 rows (16/warp), KV tile 64, dh=64.
// Ks [dh][kv] stride 72 with XOR swizzle; Vs [kv][dh] stride 72;
// Ps [qrow][kv] stride 72 (conflict-free both directions).
// Q fragments held in registers for all 32 KV tiles.
// ---------------------------------------------------------------------------
#define AT_SMEM (3 * 64 * 72 * 4)

__global__ __launch_bounds__(128)
void flash_tf32(const float* __restrict__ qkv, float* __restrict__ out) {
    extern __shared__ uint32_t sm[];
    uint32_t* Ks = sm;                 // [64][72]
    uint32_t* Vs = sm + 64 * 72;       // [64][72]
    uint32_t* Ps = sm + 2 * 64 * 72;   // [64][72]

    int tid = threadIdx.x, lane = tid & 31, wid = tid >> 5;
    int g = lane >> 2, t = lane & 3;
    int n0 = blockIdx.x * 64;
    int hh = blockIdx.y;
    int b  = blockIdx.z;

    const float* qbase = qkv + (size_t)b * SEQ * (3 * HID) + hh * DH;
    const float* kbase = qbase + HID;
    const float* vbase = qbase + 2 * HID;

    // Q fragments (scaled by 1/8), persistent in registers
    uint32_t q[8][4];
    {
        int r0 = n0 + wid * 16 + g, r1 = r0 + 8;
        #pragma unroll
        for (int ka = 0; ka < 8; ka++) {
            int c0 = ka * 8 + t;
            q[ka][0] = f2tf(qbase[(size_t)r0 * (3*HID) + c0    ] * 0.125f);
            q[ka][1] = f2tf(qbase[(size_t)r1 * (3*HID) + c0    ] * 0.125f);
            q[ka][2] = f2tf(qbase[(size_t)r0 * (3*HID) + c0 + 4] * 0.125f);
            q[ka][3] = f2tf(qbase[(size_t)r1 * (3*HID) + c0 + 4] * 0.125f);
        }
    }

    float o[8][4] = {};
    float m_lo = -1e30f, m_hi = -1e30f, l_lo = 0.f, l_hi = 0.f;

    for (int t0 = 0; t0 < SEQ; t0 += 64) {
        __syncthreads();   // protect Ks/Vs from previous iteration's readers
        // Load K (transposed+swizzled) and V
        #pragma unroll
        for (int i = 0; i < 8; i++) {
            int idx = tid + i * 128;
            int c = idx >> 4, d4 = idx & 15;
            float4 kv = *(const float4*)&kbase[(size_t)(t0 + c) * (3*HID) + d4 * 4];
            int cs = c ^ (d4 & 7);
            Ks[(d4*4+0)*72 + cs] = f2tf(kv.x);
            Ks[(d4*4+1)*72 + cs] = f2tf(kv.y);
            Ks[(d4*4+2)*72 + cs] = f2tf(kv.z);
            Ks[(d4*4+3)*72 + cs] = f2tf(kv.w);
            float4 vv = *(const float4*)&vbase[(size_t)(t0 + c) * (3*HID) + d4 * 4];
            uint4 u;
            u.x = f2tf(vv.x); u.y = f2tf(vv.y); u.z = f2tf(vv.z); u.w = f2tf(vv.w);
            *(uint4*)&Vs[c * 72 + d4 * 4] = u;
        }
        __syncthreads();

        // S = Q K^T
        float s[8][4] = {};
        #pragma unroll
        for (int ka = 0; ka < 8; ka++) {
            int kb = ka * 8;
            int s0 = (2 * ka) & 7, s1 = (2 * ka + 1) & 7;
            #pragma unroll
            for (int bn = 0; bn < 8; bn++) {
                uint32_t b0 = Ks[(kb + t    ) * 72 + ((bn*8 + g) ^ s0)];
                uint32_t b1 = Ks[(kb + t + 4) * 72 + ((bn*8 + g) ^ s1)];
                mma8(s[bn], q[ka], b0, b1);
            }
        }

        // Online softmax (row stats across the 4-lane quad)
        float mx_lo = -1e30f, mx_hi = -1e30f;
        #pragma unroll
        for (int bn = 0; bn < 8; bn++) {
            mx_lo = fmaxf(mx_lo, fmaxf(s[bn][0], s[bn][1]));
            mx_hi = fmaxf(mx_hi, fmaxf(s[bn][2], s[bn][3]));
        }
        mx_lo = fmaxf(mx_lo, __shfl_xor_sync(0xffffffffu, mx_lo, 1));
        mx_lo = fmaxf(mx_lo, __shfl_xor_sync(0xffffffffu, mx_lo, 2));
        mx_hi = fmaxf(mx_hi, __shfl_xor_sync(0xffffffffu, mx_hi, 1));
        mx_hi = fmaxf(mx_hi, __shfl_xor_sync(0xffffffffu, mx_hi, 2));

        float mn_lo = fmaxf(m_lo, mx_lo), mn_hi = fmaxf(m_hi, mx_hi);
        float corr_lo = __expf(m_lo - mn_lo), corr_hi = __expf(m_hi - mn_hi);
        float rs_lo = 0.f, rs_hi = 0.f;
        int rl = (wid * 16 + g) * 72, rh = (wid * 16 + g + 8) * 72;
        #pragma unroll
        for (int bn = 0; bn < 8; bn++) {
            float p0 = __expf(s[bn][0] - mn_lo);
            float p1 = __expf(s[bn][1] - mn_lo);
            float p2 = __expf(s[bn][2] - mn_hi);
            float p3 = __expf(s[bn][3] - mn_hi);
            rs_lo += p0 + p1; rs_hi += p2 + p3;
            int cc = bn * 8 + 2 * t;
            Ps[rl + cc]     = f2tf(p0);
            Ps[rl + cc + 1] = f2tf(p1);
            Ps[rh + cc]     = f2tf(p2);
            Ps[rh + cc + 1] = f2tf(p3);
        }
        rs_lo += __shfl_xor_sync(0xffffffffu, rs_lo, 1);
        rs_lo += __shfl_xor_sync(0xffffffffu, rs_lo, 2);
        rs_hi += __shfl_xor_sync(0xffffffffu, rs_hi, 1);
        rs_hi += __shfl_xor_sync(0xffffffffu, rs_hi, 2);
        l_lo = l_lo * corr_lo + rs_lo;  m_lo = mn_lo;
        l_hi = l_hi * corr_hi + rs_hi;  m_hi = mn_hi;
        #pragma unroll
        for (int bn = 0; bn < 8; bn++) {
            o[bn][0] *= corr_lo; o[bn][1] *= corr_lo;
            o[bn][2] *= corr_hi; o[bn][3] *= corr_hi;
        }
        __syncwarp();   // P written/read by same warp only

        // O += P V
        #pragma unroll
        for (int ka = 0; ka < 8; ka++) {
            uint32_t a[4];
            a[0] = Ps[rl + ka*8 + t];
            a[1] = Ps[rh + ka*8 + t];
            a[2] = Ps[rl + ka*8 + t + 4];
            a[3] = Ps[rh + ka*8 + t + 4];
            #pragma unroll
            for (int bn = 0; bn < 8; bn++) {
                uint32_t b0 = Vs[(ka*8 + t    ) * 72 + bn*8 + g];
                uint32_t b1 = Vs[(ka*8 + t + 4) * 72 + bn*8 + g];
                mma8(o[bn], a, b0, b1);
            }
        }
    }

    float inv_lo = 1.0f / l_lo, inv_hi = 1.0f / l_hi;
    int row = b * SEQ + n0 + wid * 16 + g;
    #pragma unroll
    for (int bn = 0; bn < 8; bn++) {
        int col = hh * DH + bn * 8 + 2 * t;
        float2 lo, hi;
        lo.x = o[bn][0] * inv_lo; lo.y = o[bn][1] * inv_lo;
        hi.x = o[bn][2] * inv_hi; hi.y = o[bn][3] * inv_hi;
        *(float2*)&out[(size_t)row * HID + col]       = lo;
        *(float2*)&out[(size_t)(row + 8) * HID + col] = hi;
    }
}

// ---------------------------------------------------------------------------
// Host launch
// ---------------------------------------------------------------------------
extern "C" void kernel_launch(void* const* d_in, const int* in_sizes, int n_in,
                              void* d_out, int out_size) {
    const float* x  = (const float*)d_in[0];
    const int*   ei = (const int*)  d_in[1];
    const float* Wg = (const float*)d_in[2];
    const float* bg = (const float*)d_in[3];
    const float* wi = (const float*)d_in[4];
    const float* bi = (const float*)d_in[5];
    const float* wo = (const float*)d_in[6];
    const float* bo = (const float*)d_in[7];
    const float* fw = (const float*)d_in[8];
    const float* fb = (const float*)d_in[9];
    float* out = (float*)d_out;
    int E = in_sizes[1] / 2;

    void *p_xl, *p_h, *p_qkv, *p_ao, *p_proj;
    cudaGetSymbolAddress(&p_xl,   g_xl);
    cudaGetSymbolAddress(&p_h,    g_h);
    cudaGetSymbolAddress(&p_qkv,  g_qkv);
    cudaGetSymbolAddress(&p_ao,   g_ao);
    cudaGetSymbolAddress(&p_proj, g_proj);

    cudaFuncSetAttribute(flash_tf32, cudaFuncAttributeMaxDynamicSharedMemorySize, AT_SMEM);

    // 1) Graph structure
    k_zero <<<(SEQ + 255) / 256, 256>>>();
    k_count<<<(E   + 255) / 256, 256>>>(ei + E, E);
    k_dinv <<<(SEQ + 255) / 256, 256>>>();
    k_fill <<<(E   + 255) / 256, 256>>>(ei, ei + E, E);

    // 2) GCN linear: xl = x @ W_gcn  (NN)
    gemm_tf32<false, false, false><<<dim3(HID / 64, TOK / 128), 256>>>(
        x, Wg, nullptr, (float*)p_xl, TOK, HID, DIN);

    // 3) GCN aggregation (+bias)
    k_agg<<<dim3(SEQ, BATCH), 128>>>(bg);

    // 4) QKV: qkv = h @ wi^T + bi  (NT)
    gemm_tf32<true, true, false><<<dim3(3 * HID / 64, TOK / 128), 256>>>(
        (const float*)p_h, wi, bi, (float*)p_qkv, TOK, 3 * HID, HID);

    // 5) Flash attention (tf32 tensor cores)
    flash_tf32<<<dim3(SEQ / 64, NHEAD, BATCH), 128, AT_SMEM>>>(
        (const float*)p_qkv, (float*)p_ao);

    // 6) out_proj + relu  (NT)
    gemm_tf32<true, true, true><<<dim3(HID / 64, TOK / 128), 256>>>(
        (const float*)p_ao, wo, bo, (float*)p_proj, TOK, HID, HID);

    // 7) fc: out = proj @ fw + fb  (NN)
    gemm_tf32<false, true, false><<<dim3(DOUT / 64, TOK / 128), 256>>>(
        (const float*)p_proj, fw, fb, out, TOK, DOUT, HID);
}

// round 4
// speedup vs baseline: 3.1629x; 1.2691x over previous
#include <cuda_runtime.h>
#include <math.h>
#include <stdint.h>

// ---------------------------------------------------------------------------
// Problem constants
// ---------------------------------------------------------------------------
#define BATCH 4
#define SEQ   2048
#define DIN   256
#define HID   512
#define DOUT  256
#define NHEAD 8
#define DH    64
#define CAP   128
#define TOK   (BATCH*SEQ)

// ---------------------------------------------------------------------------
// Scratch (tf32-bit buffers stored as float)
// ---------------------------------------------------------------------------
__device__ float g_xt  [TOK*DIN];      // x, tf32 bits
__device__ float g_wgt [HID*DIN];      // W_gcn^T, tf32 bits  [512][256]
__device__ float g_wit [3*HID*HID];    // in_proj_w, tf32 bits [1536][512]
__device__ float g_wot [HID*HID];      // out_proj_w, tf32 bits [512][512]
__device__ float g_fwt [DOUT*HID];     // fc_w^T, tf32 bits [256][512]
__device__ float g_xl  [TOK*HID];      // x @ W_gcn (fp32)
__device__ float g_h   [TOK*HID];      // GCN out (tf32 bits)
__device__ float g_qkv [TOK*3*HID];    // QKV (tf32 bits, Q pre-scaled by 1/8)
__device__ float g_ao  [TOK*HID];      // attention out (tf32 bits)
__device__ float g_proj[TOK*HID];      // out_proj+relu (tf32 bits)
__device__ float g_dinv[SEQ];
__device__ int   g_cur [SEQ];
__device__ int   g_slot[SEQ*CAP];

// ---------------------------------------------------------------------------
// Helpers
// ---------------------------------------------------------------------------
__device__ __forceinline__ uint32_t f2tf(float x) {
    uint32_t u;
    asm("cvt.rna.tf32.f32 %0, %1;" : "=r"(u) : "f"(x));
    return u;
}

__device__ __forceinline__ void mma8(float* c, const uint32_t* a,
                                     uint32_t b0, uint32_t b1) {
    asm volatile(
        "mma.sync.aligned.m16n8k8.row.col.f32.tf32.tf32.f32 "
        "{%0,%1,%2,%3}, {%4,%5,%6,%7}, {%8,%9}, {%0,%1,%2,%3};"
        : "+f"(c[0]), "+f"(c[1]), "+f"(c[2]), "+f"(c[3])
        : "r"(a[0]), "r"(a[1]), "r"(a[2]), "r"(a[3]), "r"(b0), "r"(b1));
}

__device__ __forceinline__ void cpa16(void* smem, const void* g) {
    uint32_t s = (uint32_t)__cvta_generic_to_shared(smem);
    asm volatile("cp.async.cg.shared.global [%0], [%1], 16;" :: "r"(s), "l"(g));
}

// ---------------------------------------------------------------------------
// Prep: convert / transpose-convert to tf32 bits
// ---------------------------------------------------------------------------
__global__ void k_cvt4(const float* __restrict__ src, float* __restrict__ dst, int n4) {
    int i = blockIdx.x * blockDim.x + threadIdx.x;
    if (i < n4) {
        float4 v = ((const float4*)src)[i];
        uint4 u;
        u.x = f2tf(v.x); u.y = f2tf(v.y); u.z = f2tf(v.z); u.w = f2tf(v.w);
        ((uint4*)dst)[i] = u;
    }
}

// dst[C][R] = tf32(src[R][C])
__global__ void k_tpc(const float* __restrict__ src, float* __restrict__ dst, int R, int C) {
    __shared__ float tile[32][33];
    int c0 = blockIdx.x * 32, r0 = blockIdx.y * 32;
    int tx = threadIdx.x, ty = threadIdx.y;
    #pragma unroll
    for (int i = 0; i < 32; i += 8)
        tile[ty + i][tx] = src[(size_t)(r0 + ty + i) * C + c0 + tx];
    __syncthreads();
    #pragma unroll
    for (int i = 0; i < 32; i += 8)
        dst[(size_t)(c0 + ty + i) * R + r0 + tx] =
            __uint_as_float(f2tf(tile[tx][ty + i]));
}

// ---------------------------------------------------------------------------
// Graph bookkeeping (k_fill doubles as degree counter via g_cur)
// ---------------------------------------------------------------------------
__global__ void k_zero() {
    int i = blockIdx.x * blockDim.x + threadIdx.x;
    if (i < SEQ) g_cur[i] = 0;
}
__global__ void k_fill(const int* __restrict__ src, const int* __restrict__ dst, int E) {
    int i = blockIdx.x * blockDim.x + threadIdx.x;
    if (i < E) {
        int d = dst[i];
        int p = atomicAdd(&g_cur[d], 1);
        if (p < CAP) g_slot[d * CAP + p] = src[i];
    }
}
__global__ void k_dinv() {
    int i = blockIdx.x * blockDim.x + threadIdx.x;
    if (i < SEQ) g_dinv[i] = rsqrtf((float)(g_cur[i] + 1));
}

// ---------------------------------------------------------------------------
// GCN aggregation (fp32 math, tf32-bit output)
// ---------------------------------------------------------------------------
__global__ void k_agg(const float* __restrict__ bias) {
    int n = blockIdx.x, b = blockIdx.y, t = threadIdx.x;
    const float4* x4 = (const float4*)g_xl;
    size_t base = (size_t)b * SEQ * (HID/4);
    int cnt = g_cur[n]; if (cnt > CAP) cnt = CAP;
    float4 acc = make_float4(0.f, 0.f, 0.f, 0.f);
    const int* slot = &g_slot[n * CAP];
    for (int e = 0; e < cnt; e++) {
        int s = slot[e];
        float w = g_dinv[s];
        float4 v = x4[base + (size_t)s * (HID/4) + t];
        acc.x += w * v.x; acc.y += w * v.y; acc.z += w * v.z; acc.w += w * v.w;
    }
    float dv = g_dinv[n], dv2 = dv * dv;
    float4 self = x4[base + (size_t)n * (HID/4) + t];
    float4 bs = ((const float4*)bias)[t];
    uint4 r;
    r.x = f2tf(dv * acc.x + dv2 * self.x + bs.x);
    r.y = f2tf(dv * acc.y + dv2 * self.y + bs.y);
    r.z = f2tf(dv * acc.z + dv2 * self.z + bs.z);
    r.w = f2tf(dv * acc.w + dv2 * self.w + bs.w);
    ((uint4*)g_h)[base + (size_t)n * (HID/4) + t] = r;
}

// ---------------------------------------------------------------------------
// Double-buffered tf32 GEMM. All operands tf32 bits, B stored [Nn][K].
// BM=128 BN=64 BK=32, 256 threads = 8 warps (4M x 2N), warp tile 32x32.
// Smem unpadded with chunk-XOR swizzle: word (row, c) at row*32 + ((c>>2)^(row&7))*4 + (c&3).
// Fragment load banks: ((X^g)*4 + t) -> all 32 distinct.
// ---------------------------------------------------------------------------
template<bool BIAS, bool RELU, bool OCVT, bool SCALEQ>
__global__ __launch_bounds__(256)
void gemm_mma(const uint32_t* __restrict__ A, const uint32_t* __restrict__ B,
              const float* __restrict__ bias, float* __restrict__ C,
              int M, int Nn, int K) {
    __shared__ uint32_t As[2][128*32];
    __shared__ uint32_t Bs[2][64*32];
    int tid = threadIdx.x, lane = tid & 31, wid = tid >> 5;
    int g = lane >> 2, t = lane & 3;
    int wm = wid >> 1, wn = wid & 1;
    int mBase = blockIdx.y * 128, nBase = blockIdx.x * 64;
    float acc[2][4][4] = {};
    int T = K >> 5;

    auto load_stage = [&](int kt, int st) {
        const uint32_t* Ag = A + (size_t)mBase * K + kt * 32;
        #pragma unroll
        for (int i = 0; i < 4; i++) {
            int idx = tid + i * 256;
            int m = idx >> 3, c4 = idx & 7;
            cpa16(&As[st][m * 32 + ((c4 ^ (m & 7)) << 2)], Ag + (size_t)m * K + c4 * 4);
        }
        const uint32_t* Bg = B + (size_t)nBase * K + kt * 32;
        #pragma unroll
        for (int i = 0; i < 2; i++) {
            int idx = tid + i * 256;
            int n = idx >> 3, c4 = idx & 7;
            cpa16(&Bs[st][n * 32 + ((c4 ^ (n & 7)) << 2)], Bg + (size_t)n * K + c4 * 4);
        }
        asm volatile("cp.async.commit_group;");
    };

    load_stage(0, 0);
    for (int kt = 0; kt < T; kt++) {
        int st = kt & 1;
        if (kt + 1 < T) {
            load_stage(kt + 1, st ^ 1);
            asm volatile("cp.async.wait_group 1;");
        } else {
            asm volatile("cp.async.wait_group 0;");
        }
        __syncthreads();
        const uint32_t* as = As[st];
        const uint32_t* bs = Bs[st];
        #pragma unroll
        for (int ks = 0; ks < 4; ks++) {
            int X0 = 2 * ks, X1 = 2 * ks + 1;
            uint32_t a[2][4];
            #pragma unroll
            for (int am = 0; am < 2; am++) {
                int r0 = (wm * 32 + am * 16 + g) * 32;
                int r1 = r0 + 8 * 32;
                a[am][0] = as[r0 + ((X0 ^ g) << 2) + t];
                a[am][1] = as[r1 + ((X0 ^ g) << 2) + t];
                a[am][2] = as[r0 + ((X1 ^ g) << 2) + t];
                a[am][3] = as[r1 + ((X1 ^ g) << 2) + t];
            }
            #pragma unroll
            for (int bn = 0; bn < 4; bn++) {
                int nr = (wn * 32 + bn * 8 + g) * 32;
                uint32_t b0 = bs[nr + ((X0 ^ g) << 2) + t];
                uint32_t b1 = bs[nr + ((X1 ^ g) << 2) + t];
                mma8(acc[0][bn], a[0], b0, b1);
                mma8(acc[1][bn], a[1], b0, b1);
            }
        }
        __syncthreads();
    }

    #pragma unroll
    for (int am = 0; am < 2; am++) {
        #pragma unroll
        for (int bn = 0; bn < 4; bn++) {
            int row = mBase + wm * 32 + am * 16 + g;
            int col = nBase + wn * 32 + bn * 8 + 2 * t;
            float b0v = 0.f, b1v = 0.f;
            if (BIAS) { b0v = bias[col]; b1v = bias[col + 1]; }
            float sc = 1.f;
            if (SCALEQ) sc = (col < HID) ? 0.125f : 1.f;
            float v00 = (acc[am][bn][0] + b0v) * sc;
            float v01 = (acc[am][bn][1] + b1v) * sc;
            float v10 = (acc[am][bn][2] + b0v) * sc;
            float v11 = (acc[am][bn][3] + b1v) * sc;
            if (RELU) {
                v00 = fmaxf(v00, 0.f); v01 = fmaxf(v01, 0.f);
                v10 = fmaxf(v10, 0.f); v11 = fmaxf(v11, 0.f);
            }
            float2 lo, hi;
            if (OCVT) {
                lo.x = __uint_as_float(f2tf(v00)); lo.y = __uint_as_float(f2tf(v01));
                hi.x = __uint_as_float(f2tf(v10)); hi.y = __uint_as_float(f2tf(v11));
            } else {
                lo.x = v00; lo.y = v01; hi.x = v10; hi.y = v11;
            }
            *(float2*)&C[(size_t)row * Nn + col]       = lo;
            *(float2*)&C[(size_t)(row + 8) * Nn + col] = hi;
        }
    }
}

// ---------------------------------------------------------------------------
// Flash attention, tf32 tensor cores. Q tile 128 rows, KV tile 64, dh=64.
// 256 threads = 8 warps, each owning 16 q rows. qkv is tf32 bits (Q pre-scaled).
// Ks [token][dh] stride 68 (S-mma B frags conflict-free: banks 4g+t).
// Vs [token][dh] stride 72 (PV-mma B frags conflict-free: banks 8t+8bn+g).
// Ps [qrow][kv] stride 72, per-warp private rows (syncwarp only).
// ---------------------------------------------------------------------------
#define KS_STRIDE 68
#define VS_STRIDE 72
#define PS_STRIDE 72
#define AT_SMEM ((64*KS_STRIDE + 64*VS_STRIDE + 128*PS_STRIDE) * 4)

__global__ __launch_bounds__(256, 2)
void flash_tf32(const uint32_t* __restrict__ qkv, float* __restrict__ out) {
    extern __shared__ uint32_t sm[];
    uint32_t* Ks = sm;
    uint32_t* Vs = sm + 64 * KS_STRIDE;
    uint32_t* Ps = sm + 64 * KS_STRIDE + 64 * VS_STRIDE;

    int tid = threadIdx.x, lane = tid & 31, wid = tid >> 5;
    int g = lane >> 2, t = lane & 3;
    int n0 = blockIdx.x * 128;
    int hh = blockIdx.y, b = blockIdx.z;

    const uint32_t* qbase = qkv + (size_t)b * SEQ * (3 * HID) + hh * DH;
    const uint32_t* kbase = qbase + HID;
    const uint32_t* vbase = qbase + 2 * HID;

    // Q fragments (already tf32 bits, scale 1/8 already applied in QKV epilogue)
    uint32_t q[8][4];
    int r0g = n0 + wid * 16 + g;
    #pragma unroll
    for (int ka = 0; ka < 8; ka++) {
        int c0 = ka * 8 + t;
        q[ka][0] = qbase[(size_t)r0g       * (3*HID) + c0];
        q[ka][1] = qbase[(size_t)(r0g + 8) * (3*HID) + c0];
        q[ka][2] = qbase[(size_t)r0g       * (3*HID) + c0 + 4];
        q[ka][3] = qbase[(size_t)(r0g + 8) * (3*HID) + c0 + 4];
    }

    float o[8][4] = {};
    float m_lo = -1e30f, m_hi = -1e30f, l_lo = 0.f, l_hi = 0.f;
    int rl = (wid * 16 + g) * PS_STRIDE, rh = rl + 8 * PS_STRIDE;

    for (int t0 = 0; t0 < SEQ; t0 += 64) {
        __syncthreads();
        // Load K/V tiles: straight uint4 copies (no cvt, no transpose)
        #pragma unroll
        for (int i = 0; i < 4; i++) {
            int idx = tid + i * 256;
            int c = idx >> 4, d4 = idx & 15;
            uint4 kv = *(const uint4*)&kbase[(size_t)(t0 + c) * (3*HID) + d4 * 4];
            *(uint4*)&Ks[c * KS_STRIDE + d4 * 4] = kv;
            uint4 vv = *(const uint4*)&vbase[(size_t)(t0 + c) * (3*HID) + d4 * 4];
            *(uint4*)&Vs[c * VS_STRIDE + d4 * 4] = vv;
        }
        __syncthreads();

        // S = Q K^T
        float s[8][4] = {};
        #pragma unroll
        for (int ka = 0; ka < 8; ka++) {
            int kb = ka * 8;
            #pragma unroll
            for (int bn = 0; bn < 8; bn++) {
                const uint32_t* kr = &Ks[(bn * 8 + g) * KS_STRIDE + kb + t];
                mma8(s[bn], q[ka], kr[0], kr[4]);
            }
        }

        // Online softmax (row stats across 4-lane quad)
        float mx_lo = -1e30f, mx_hi = -1e30f;
        #pragma unroll
        for (int bn = 0; bn < 8; bn++) {
            mx_lo = fmaxf(mx_lo, fmaxf(s[bn][0], s[bn][1]));
            mx_hi = fmaxf(mx_hi, fmaxf(s[bn][2], s[bn][3]));
        }
        mx_lo = fmaxf(mx_lo, __shfl_xor_sync(0xffffffffu, mx_lo, 1));
        mx_lo = fmaxf(mx_lo, __shfl_xor_sync(0xffffffffu, mx_lo, 2));
        mx_hi = fmaxf(mx_hi, __shfl_xor_sync(0xffffffffu, mx_hi, 1));
        mx_hi = fmaxf(mx_hi, __shfl_xor_sync(0xffffffffu, mx_hi, 2));

        float mn_lo = fmaxf(m_lo, mx_lo), mn_hi = fmaxf(m_hi, mx_hi);
        float corr_lo = __expf(m_lo - mn_lo), corr_hi = __expf(m_hi - mn_hi);
        float rs_lo = 0.f, rs_hi = 0.f;
        #pragma unroll
        for (int bn = 0; bn < 8; bn++) {
            float p0 = __expf(s[bn][0] - mn_lo);
            float p1 = __expf(s[bn][1] - mn_lo);
            float p2 = __expf(s[bn][2] - mn_hi);
            float p3 = __expf(s[bn][3] - mn_hi);
            rs_lo += p0 + p1; rs_hi += p2 + p3;
            int cc = bn * 8 + 2 * t;
            Ps[rl + cc]     = f2tf(p0);
            Ps[rl + cc + 1] = f2tf(p1);
            Ps[rh + cc]     = f2tf(p2);
            Ps[rh + cc + 1] = f2tf(p3);
        }
        rs_lo += __shfl_xor_sync(0xffffffffu, rs_lo, 1);
        rs_lo += __shfl_xor_sync(0xffffffffu, rs_lo, 2);
        rs_hi += __shfl_xor_sync(0xffffffffu, rs_hi, 1);
        rs_hi += __shfl_xor_sync(0xffffffffu, rs_hi, 2);
        l_lo = l_lo * corr_lo + rs_lo;  m_lo = mn_lo;
        l_hi = l_hi * corr_hi + rs_hi;  m_hi = mn_hi;
        #pragma unroll
        for (int bn = 0; bn < 8; bn++) {
            o[bn][0] *= corr_lo; o[bn][1] *= corr_lo;
            o[bn][2] *= corr_hi; o[bn][3] *= corr_hi;
        }
        __syncwarp();   // Ps rows are warp-private

        // O += P V
        #pragma unroll
        for (int ka = 0; ka < 8; ka++) {
            uint32_t a[4];
            a[0] = Ps[rl + ka*8 + t];
            a[1] = Ps[rh + ka*8 + t];
            a[2] = Ps[rl + ka*8 + t + 4];
            a[3] = Ps[rh + ka*8 + t + 4];
            #pragma unroll
            for (int bn = 0; bn < 8; bn++) {
                uint32_t b0 = Vs[(ka*8 + t)     * VS_STRIDE + bn*8 + g];
                uint32_t b1 = Vs[(ka*8 + t + 4) * VS_STRIDE + bn*8 + g];
                mma8(o[bn], a, b0, b1);
            }
        }
    }

    float inv_lo = 1.0f / l_lo, inv_hi = 1.0f / l_hi;
    int row = b * SEQ + n0 + wid * 16 + g;
    #pragma unroll
    for (int bn = 0; bn < 8; bn++) {
        int col = hh * DH + bn * 8 + 2 * t;
        float2 lo, hi;
        lo.x = __uint_as_float(f2tf(o[bn][0] * inv_lo));
        lo.y = __uint_as_float(f2tf(o[bn][1] * inv_lo));
        hi.x = __uint_as_float(f2tf(o[bn][2] * inv_hi));
        hi.y = __uint_as_float(f2tf(o[bn][3] * inv_hi));
        *(float2*)&out[(size_t)row * HID + col]       = lo;
        *(float2*)&out[(size_t)(row + 8) * HID + col] = hi;
    }
}

// ---------------------------------------------------------------------------
// Host launch
// ---------------------------------------------------------------------------
extern "C" void kernel_launch(void* const* d_in, const int* in_sizes, int n_in,
                              void* d_out, int out_size) {
    const float* x  = (const float*)d_in[0];
    const int*   ei = (const int*)  d_in[1];
    const float* Wg = (const float*)d_in[2];
    const float* bg = (const float*)d_in[3];
    const float* wi = (const float*)d_in[4];
    const float* bi = (const float*)d_in[5];
    const float* wo = (const float*)d_in[6];
    const float* bo = (const float*)d_in[7];
    const float* fw = (const float*)d_in[8];
    const float* fb = (const float*)d_in[9];
    float* out = (float*)d_out;
    int E = in_sizes[1] / 2;

    void *p_xt, *p_wgt, *p_wit, *p_wot, *p_fwt;
    void *p_xl, *p_h, *p_qkv, *p_ao, *p_proj;
    cudaGetSymbolAddress(&p_xt,   g_xt);
    cudaGetSymbolAddress(&p_wgt,  g_wgt);
    cudaGetSymbolAddress(&p_wit,  g_wit);
    cudaGetSymbolAddress(&p_wot,  g_wot);
    cudaGetSymbolAddress(&p_fwt,  g_fwt);
    cudaGetSymbolAddress(&p_xl,   g_xl);
    cudaGetSymbolAddress(&p_h,    g_h);
    cudaGetSymbolAddress(&p_qkv,  g_qkv);
    cudaGetSymbolAddress(&p_ao,   g_ao);
    cudaGetSymbolAddress(&p_proj, g_proj);

    cudaFuncSetAttribute(flash_tf32, cudaFuncAttributeMaxDynamicSharedMemorySize, AT_SMEM);

    // 1) Graph structure (k_fill also produces degree counts in g_cur)
    k_zero<<<(SEQ + 255) / 256, 256>>>();
    k_fill<<<(E + 255) / 256, 256>>>(ei, ei + E, E);
    k_dinv<<<(SEQ + 255) / 256, 256>>>();

    // 2) Pre-convert operands to tf32 bits (transpose NN-weights to [n][k])
    k_cvt4<<<(TOK*DIN/4 + 255) / 256, 256>>>(x,  (float*)p_xt,  TOK*DIN/4);
    k_cvt4<<<(3*HID*HID/4 + 255) / 256, 256>>>(wi, (float*)p_wit, 3*HID*HID/4);
    k_cvt4<<<(HID*HID/4 + 255) / 256, 256>>>(wo, (float*)p_wot, HID*HID/4);
    k_tpc<<<dim3(HID/32, DIN/32), dim3(32, 8)>>>(Wg, (float*)p_wgt, DIN, HID);
    k_tpc<<<dim3(DOUT/32, HID/32), dim3(32, 8)>>>(fw, (float*)p_fwt, HID, DOUT);

    // 3) GCN linear: xl = x @ W_gcn (fp32 out, feeds fp32 aggregation)
    gemm_mma<false, false, false, false><<<dim3(HID/64, TOK/128), 256>>>(
        (const uint32_t*)p_xt, (const uint32_t*)p_wgt, nullptr, (float*)p_xl,
        TOK, HID, DIN);

    // 4) GCN aggregation (+bias), tf32-bit output
    k_agg<<<dim3(SEQ, BATCH), 128>>>(bg);

    // 5) QKV (+bias, Q scaled 1/8, tf32-bit output)
    gemm_mma<true, false, true, true><<<dim3(3*HID/64, TOK/128), 256>>>(
        (const uint32_t*)p_h, (const uint32_t*)p_wit, bi, (float*)p_qkv,
        TOK, 3*HID, HID);

    // 6) Flash attention (tf32-bit output)
    flash_tf32<<<dim3(SEQ/128, NHEAD, BATCH), 256, AT_SMEM>>>(
        (const uint32_t*)p_qkv, (float*)p_ao);

    // 7) out_proj + relu (tf32-bit output)
    gemm_mma<true, true, true, false><<<dim3(HID/64, TOK/128), 256>>>(
        (const uint32_t*)p_ao, (const uint32_t*)p_wot, bo, (float*)p_proj,
        TOK, HID, HID);

    // 8) fc: out = proj @ fw + fb (fp32 output)
    gemm_mma<true, false, false, false><<<dim3(DOUT/64, TOK/128), 256>>>(
        (const uint32_t*)p_proj, (const uint32_t*)p_fwt, fb, out,
        TOK, DOUT, HID);
}